// round 10
// baseline (speedup 1.0000x reference)
#include <cuda_runtime.h>
#include <cuda_fp16.h>
#include <cstdint>

#define IN_DIM  8192
#define OUT_DIM 8192
#define BATCH   8192
#define R       2                        // rows per group (pair-interleaved in smem)
#define THREADS 1024
#define NGROUPS (BATCH / R)              // 4096, exact
#define GRID    148
#define KITERS  (OUT_DIM / THREADS)      // 8 j's per thread
// smem: double-buffered interleaved row pair: 2 * (2*8192) floats = 128 KB
#define SMEM_BYTES (2 * R * IN_DIM * 4)

// Meta SoA in gmem (filled by prep; each block loads its slice into REGISTERS).
__device__ unsigned g_mIdx[OUT_DIM];   // idx_a | idx_b<<13
__device__ unsigned g_mC01[OUT_DIM];   // half2(c0, c1)
__device__ unsigned g_mC23[OUT_DIM];   // half2(c2, c3)
__device__ unsigned g_ctr;             // work-stealing counter

// GATE_COEFFS columns (16 rows x 4 cols, column-wise)
__constant__ float GATE0[16] = {0,0,0,0,0,0,0,0, 1, 1, 1, 1, 1, 1, 1, 1};
__constant__ float GATE1[16] = {0,0,1,1,0,0,1,1,-1,-1, 0, 0,-1,-1, 0, 0};
__constant__ float GATE2[16] = {0,0,0,0,1,1,1,1,-1,-1,-1,-1, 0, 0, 0, 0};
__constant__ float GATE3[16] = {0,1,-1,0,-1,0,-2,-1, 1, 2, 0, 1, 0, 1,-1, 0};

// ---------------------------------------------------------------------------
// Prep: softmax(weight[j]) @ GATE -> packed SoA meta; reset steal counter.
// ---------------------------------------------------------------------------
__global__ void prep_kernel(const float* __restrict__ weight,
                            const int* __restrict__ idx_a,
                            const int* __restrict__ idx_b) {
    int j = blockIdx.x * blockDim.x + threadIdx.x;
    if (j == 0) g_ctr = 0;
    if (j >= OUT_DIM) return;

    const float4* wrow = reinterpret_cast<const float4*>(weight + (size_t)j * 16);
    float v[16];
    #pragma unroll
    for (int q = 0; q < 4; q++) {
        float4 w = wrow[q];
        v[q*4+0] = w.x; v[q*4+1] = w.y; v[q*4+2] = w.z; v[q*4+3] = w.w;
    }
    float m = v[0];
    #pragma unroll
    for (int k = 1; k < 16; k++) m = fmaxf(m, v[k]);
    float s = 0.0f;
    #pragma unroll
    for (int k = 0; k < 16; k++) { v[k] = expf(v[k] - m); s += v[k]; }
    float inv = 1.0f / s;

    float c0 = 0.f, c1 = 0.f, c2 = 0.f, c3 = 0.f;
    #pragma unroll
    for (int k = 0; k < 16; k++) {
        float wk = v[k] * inv;
        c0 = fmaf(wk, GATE0[k], c0);
        c1 = fmaf(wk, GATE1[k], c1);
        c2 = fmaf(wk, GATE2[k], c2);
        c3 = fmaf(wk, GATE3[k], c3);
    }

    g_mIdx[j] = (unsigned)idx_a[j] | ((unsigned)idx_b[j] << 13);
    __half2 c01 = __floats2half2_rn(c0, c1);
    __half2 c23 = __floats2half2_rn(c2, c3);
    g_mC01[j] = *reinterpret_cast<unsigned*>(&c01);
    g_mC23[j] = *reinterpret_cast<unsigned*>(&c23);
}

// ---------------------------------------------------------------------------
// Copy chunk c (of 4) of group g's row pair into interleaved smem buffer.
// Each thread: 2 consecutive elements of both rows -> one conflict-free STS.128.
//   dst layout: float2 at index i holds (row0[i], row1[i]).
// ---------------------------------------------------------------------------
__device__ __forceinline__ void copy_chunk(float* __restrict__ dst,
                                           const float* __restrict__ x,
                                           int g, int c, int tid) {
    const float* base = x + (size_t)g * (R * IN_DIM);
    int e0 = 2 * (c * THREADS + tid);          // element index (0..8190, step 2)
    float2 r0 = __ldcs(reinterpret_cast<const float2*>(base + e0));
    float2 r1 = __ldcs(reinterpret_cast<const float2*>(base + IN_DIM + e0));
    float4 w = make_float4(r0.x, r1.x, r0.y, r1.y);
    *reinterpret_cast<float4*>(dst + 2 * e0) = w;   // STS.128, 16B-stride lanes
}

// ---------------------------------------------------------------------------
// Main: persistent, meta in registers, pair-interleaved double-buffered rows,
// copy chunks interleaved with compute, work-stealing.
// ---------------------------------------------------------------------------
extern "C" __global__ void __launch_bounds__(THREADS, 1)
logic_kernel(const float* __restrict__ x, float* __restrict__ out) {
    extern __shared__ float sm[];             // [2][2*IN_DIM] interleaved pairs
    __shared__ int s_g;
    const int tid = threadIdx.x;

    // ---- Load this thread's meta slice into registers (once) ----
    unsigned mIdx[KITERS], mC01[KITERS], mC23[KITERS];
    #pragma unroll
    for (int k = 0; k < KITERS; k++) {
        int j = tid + k * THREADS;
        mIdx[k] = g_mIdx[j];
        mC01[k] = g_mC01[j];
        mC23[k] = g_mC23[j];
    }

    // ---- Claim first group, fill buffer 0 ----
    if (tid == 0) s_g = (int)atomicAdd(&g_ctr, 1u);
    __syncthreads();
    int g = s_g;
    if (g >= NGROUPS) return;

    int cur = 0;
    #pragma unroll
    for (int c = 0; c < 4; c++) copy_chunk(sm, x, g, c, tid);
    __syncthreads();

    while (true) {
        if (tid == 0) s_g = (int)atomicAdd(&g_ctr, 1u);
        __syncthreads();                       // s_g visible
        int next = s_g;
        bool has_next = (next < NGROUPS);

        const float2* buf = reinterpret_cast<const float2*>(sm + cur * (R * IN_DIM));
        float* nbuf = sm + (cur ^ 1) * (R * IN_DIM);
        float* o0 = out + (size_t)g * (R * OUT_DIM);

        // 4 copy chunks interleaved with 8 compute iters (2 per chunk)
        #pragma unroll
        for (int c = 0; c < 4; c++) {
            if (has_next) copy_chunk(nbuf, x, next, c, tid);
            #pragma unroll
            for (int kk = 0; kk < 2; kk++) {
                int k = 2 * c + kk;
                int j = tid + k * THREADS;
                unsigned pk = mIdx[k];
                unsigned ai = pk & 8191u;
                unsigned bi = pk >> 13;
                float2 av = buf[ai];           // LDS.64: (a_row0, a_row1)
                float2 bv = buf[bi];           // LDS.64: (b_row0, b_row1)
                float2 c01 = __half22float2(*reinterpret_cast<const __half2*>(&mC01[k]));
                float2 c23 = __half22float2(*reinterpret_cast<const __half2*>(&mC23[k]));
                __stcg(o0 + j,
                       fmaf(c23.y, av.x * bv.x, fmaf(c23.x, bv.x, fmaf(c01.y, av.x, c01.x))));
                __stcg(o0 + OUT_DIM + j,
                       fmaf(c23.y, av.y * bv.y, fmaf(c23.x, bv.y, fmaf(c01.y, av.y, c01.x))));
            }
        }

        __syncthreads();   // gathers from buf done; STS into nbuf visible
        if (!has_next) break;
        g = next;
        cur ^= 1;
    }
}

// ---------------------------------------------------------------------------
// Launch: x (f32), weight (f32), idx_a (i32), idx_b (i32) -> out (f32)
// ---------------------------------------------------------------------------
extern "C" void kernel_launch(void* const* d_in, const int* in_sizes, int n_in,
                              void* d_out, int out_size) {
    const float* x      = (const float*)d_in[0];
    const float* weight = (const float*)d_in[1];
    const int*   idx_a  = (const int*)d_in[2];
    const int*   idx_b  = (const int*)d_in[3];
    float*       out    = (float*)d_out;

    cudaFuncSetAttribute(logic_kernel,
                         cudaFuncAttributeMaxDynamicSharedMemorySize, SMEM_BYTES);

    prep_kernel<<<OUT_DIM / 256, 256>>>(weight, idx_a, idx_b);
    logic_kernel<<<GRID, THREADS, SMEM_BYTES>>>(x, out);
}

// round 15
// speedup vs baseline: 1.1207x; 1.1207x over previous
#include <cuda_runtime.h>
#include <cuda_fp16.h>
#include <cstdint>

#define IN_DIM  8192
#define OUT_DIM 8192
#define BATCH   8192
#define R       2                        // rows per group (pair-interleaved in smem)
#define THREADS 1024
#define NGROUPS (BATCH / R)              // 4096, exact
#define GRID    148
#define KITERS  (OUT_DIM / THREADS)      // 8 j's per thread
#define CHUNKS  4                        // copy chunks per group (2 LDG.64 each)
// smem: double-buffered interleaved row pair: 2 * (2*8192) floats = 128 KB
#define SMEM_BYTES (2 * R * IN_DIM * 4)

// Meta SoA in gmem (filled by prep; each block loads its slice into REGISTERS).
__device__ unsigned g_mIdx[OUT_DIM];   // idx_a | idx_b<<13
__device__ unsigned g_mC01[OUT_DIM];   // half2(c0, c1)
__device__ unsigned g_mC23[OUT_DIM];   // half2(c2, c3)
__device__ unsigned g_ctr;             // work-stealing counter

// GATE_COEFFS columns (16 rows x 4 cols, column-wise)
__constant__ float GATE0[16] = {0,0,0,0,0,0,0,0, 1, 1, 1, 1, 1, 1, 1, 1};
__constant__ float GATE1[16] = {0,0,1,1,0,0,1,1,-1,-1, 0, 0,-1,-1, 0, 0};
__constant__ float GATE2[16] = {0,0,0,0,1,1,1,1,-1,-1,-1,-1, 0, 0, 0, 0};
__constant__ float GATE3[16] = {0,1,-1,0,-1,0,-2,-1, 1, 2, 0, 1, 0, 1,-1, 0};

// ---------------------------------------------------------------------------
// Prep: softmax(weight[j]) @ GATE -> packed SoA meta; reset steal counter.
// ---------------------------------------------------------------------------
__global__ void prep_kernel(const float* __restrict__ weight,
                            const int* __restrict__ idx_a,
                            const int* __restrict__ idx_b) {
    int j = blockIdx.x * blockDim.x + threadIdx.x;
    if (j == 0) g_ctr = 0;
    if (j >= OUT_DIM) return;

    const float4* wrow = reinterpret_cast<const float4*>(weight + (size_t)j * 16);
    float v[16];
    #pragma unroll
    for (int q = 0; q < 4; q++) {
        float4 w = wrow[q];
        v[q*4+0] = w.x; v[q*4+1] = w.y; v[q*4+2] = w.z; v[q*4+3] = w.w;
    }
    float m = v[0];
    #pragma unroll
    for (int k = 1; k < 16; k++) m = fmaxf(m, v[k]);
    float s = 0.0f;
    #pragma unroll
    for (int k = 0; k < 16; k++) { v[k] = expf(v[k] - m); s += v[k]; }
    float inv = 1.0f / s;

    float c0 = 0.f, c1 = 0.f, c2 = 0.f, c3 = 0.f;
    #pragma unroll
    for (int k = 0; k < 16; k++) {
        float wk = v[k] * inv;
        c0 = fmaf(wk, GATE0[k], c0);
        c1 = fmaf(wk, GATE1[k], c1);
        c2 = fmaf(wk, GATE2[k], c2);
        c3 = fmaf(wk, GATE3[k], c3);
    }

    g_mIdx[j] = (unsigned)idx_a[j] | ((unsigned)idx_b[j] << 13);
    __half2 c01 = __floats2half2_rn(c0, c1);
    __half2 c23 = __floats2half2_rn(c2, c3);
    g_mC01[j] = *reinterpret_cast<unsigned*>(&c01);
    g_mC23[j] = *reinterpret_cast<unsigned*>(&c23);
}

// ---------------------------------------------------------------------------
// Main: persistent, meta in registers, pair-interleaved double-buffered rows.
// Per iteration: (1) LDG next rows -> regs (no consumer), (2) compute current
// buffer (covers LDG latency), (3) STS staged regs, barrier.
// ---------------------------------------------------------------------------
extern "C" __global__ void __launch_bounds__(THREADS, 1)
logic_kernel(const float* __restrict__ x, float* __restrict__ out) {
    extern __shared__ float sm[];             // [2][2*IN_DIM] interleaved pairs
    __shared__ int s_g;
    const int tid = threadIdx.x;

    // ---- Load + decode this thread's meta slice into registers (once) ----
    unsigned mIdx[KITERS];
    float2 mc01[KITERS], mc23[KITERS];
    #pragma unroll
    for (int k = 0; k < KITERS; k++) {
        int j = tid + k * THREADS;
        mIdx[k] = g_mIdx[j];
        unsigned u01 = g_mC01[j];
        unsigned u23 = g_mC23[j];
        mc01[k] = __half22float2(*reinterpret_cast<const __half2*>(&u01));
        mc23[k] = __half22float2(*reinterpret_cast<const __half2*>(&u23));
    }

    // ---- Claim first group, fill buffer 0 (startup latency exposed once) ----
    if (tid == 0) s_g = (int)atomicAdd(&g_ctr, 1u);
    __syncthreads();
    int g = s_g;
    if (g >= NGROUPS) return;

    int cur = 0;
    {
        const float* base = x + (size_t)g * (R * IN_DIM);
        #pragma unroll
        for (int c = 0; c < CHUNKS; c++) {
            int e0 = 2 * (c * THREADS + tid);
            float2 r0 = __ldcs(reinterpret_cast<const float2*>(base + e0));
            float2 r1 = __ldcs(reinterpret_cast<const float2*>(base + IN_DIM + e0));
            *reinterpret_cast<float4*>(sm + 2 * e0) = make_float4(r0.x, r1.x, r0.y, r1.y);
        }
    }
    __syncthreads();

    while (true) {
        if (tid == 0) s_g = (int)atomicAdd(&g_ctr, 1u);
        __syncthreads();                       // s_g visible
        int next = s_g;
        bool has_next = (next < NGROUPS);

        // ---- Phase 1: issue ALL next-group LDGs (no consumer yet) ----
        float2 nr0[CHUNKS], nr1[CHUNKS];
        if (has_next) {
            const float* base = x + (size_t)next * (R * IN_DIM);
            #pragma unroll
            for (int c = 0; c < CHUNKS; c++) {
                int e0 = 2 * (c * THREADS + tid);
                nr0[c] = __ldcs(reinterpret_cast<const float2*>(base + e0));
                nr1[c] = __ldcs(reinterpret_cast<const float2*>(base + IN_DIM + e0));
            }
        }

        // ---- Phase 2: compute current group (covers LDG latency) ----
        const float2* buf = reinterpret_cast<const float2*>(sm + cur * (R * IN_DIM));
        float* o0 = out + (size_t)g * (R * OUT_DIM);
        #pragma unroll
        for (int k = 0; k < KITERS; k++) {
            int j = tid + k * THREADS;
            unsigned pk = mIdx[k];
            unsigned ai = pk & 8191u;
            unsigned bi = pk >> 13;
            float2 av = buf[ai];               // LDS.64: (a_row0, a_row1)
            float2 bv = buf[bi];               // LDS.64: (b_row0, b_row1)
            float2 c01 = mc01[k];
            float2 c23 = mc23[k];
            __stcg(o0 + j,
                   fmaf(c23.y, av.x * bv.x, fmaf(c23.x, bv.x, fmaf(c01.y, av.x, c01.x))));
            __stcg(o0 + OUT_DIM + j,
                   fmaf(c23.y, av.y * bv.y, fmaf(c23.x, bv.y, fmaf(c01.y, av.y, c01.x))));
        }

        // ---- Phase 3: commit staged rows to the other buffer ----
        if (has_next) {
            float* nbuf = sm + (cur ^ 1) * (R * IN_DIM);
            #pragma unroll
            for (int c = 0; c < CHUNKS; c++) {
                int e0 = 2 * (c * THREADS + tid);
                *reinterpret_cast<float4*>(nbuf + 2 * e0) =
                    make_float4(nr0[c].x, nr1[c].x, nr0[c].y, nr1[c].y);
            }
        }

        __syncthreads();   // gathers from buf done + nbuf writes visible
        if (!has_next) break;
        g = next;
        cur ^= 1;
    }
}

// ---------------------------------------------------------------------------
// Launch: x (f32), weight (f32), idx_a (i32), idx_b (i32) -> out (f32)
// ---------------------------------------------------------------------------
extern "C" void kernel_launch(void* const* d_in, const int* in_sizes, int n_in,
                              void* d_out, int out_size) {
    const float* x      = (const float*)d_in[0];
    const float* weight = (const float*)d_in[1];
    const int*   idx_a  = (const int*)d_in[2];
    const int*   idx_b  = (const int*)d_in[3];
    float*       out    = (float*)d_out;

    cudaFuncSetAttribute(logic_kernel,
                         cudaFuncAttributeMaxDynamicSharedMemorySize, SMEM_BYTES);

    prep_kernel<<<OUT_DIM / 256, 256>>>(weight, idx_a, idx_b);
    logic_kernel<<<GRID, THREADS, SMEM_BYTES>>>(x, out);
}

// round 16
// speedup vs baseline: 1.4751x; 1.3163x over previous
#include <cuda_runtime.h>
#include <cuda_fp16.h>
#include <cstdint>

#define IN_DIM  8192
#define OUT_DIM 8192
#define BATCH   8192
#define R       2                         // rows per group (one 64KB contiguous TMA)
#define THREADS 1024
#define NGROUPS (BATCH / R)               // 4096, exact
#define GRID    148
#define KITERS  (OUT_DIM / THREADS)       // 8 j's per thread
#define GROUP_BYTES (R * IN_DIM * 4)      // 65536
// dynamic smem: double-buffered row pair: 2 * 64KB = 128 KB
#define SMEM_BYTES (2 * R * IN_DIM * 4)

// Meta in gmem: idx packed (loaded to regs once); coeffs read via __ldg (L1-resident).
__device__ unsigned g_mIdx[OUT_DIM];      // idx_a | idx_b<<13
__device__ uint2    g_coef[OUT_DIM];      // .x = half2(c0,c1), .y = half2(c2,c3)
__device__ unsigned g_ctr;                // work-stealing counter

// GATE_COEFFS columns (16 rows x 4 cols, column-wise)
__constant__ float GATE0[16] = {0,0,0,0,0,0,0,0, 1, 1, 1, 1, 1, 1, 1, 1};
__constant__ float GATE1[16] = {0,0,1,1,0,0,1,1,-1,-1, 0, 0,-1,-1, 0, 0};
__constant__ float GATE2[16] = {0,0,0,0,1,1,1,1,-1,-1,-1,-1, 0, 0, 0, 0};
__constant__ float GATE3[16] = {0,1,-1,0,-1,0,-2,-1, 1, 2, 0, 1, 0, 1,-1, 0};

// ---------------------------------------------------------------------------
// Prep: softmax(weight[j]) @ GATE -> packed meta; reset steal counter.
// ---------------------------------------------------------------------------
__global__ void prep_kernel(const float* __restrict__ weight,
                            const int* __restrict__ idx_a,
                            const int* __restrict__ idx_b) {
    int j = blockIdx.x * blockDim.x + threadIdx.x;
    if (j == 0) g_ctr = 0;
    if (j >= OUT_DIM) return;

    const float4* wrow = reinterpret_cast<const float4*>(weight + (size_t)j * 16);
    float v[16];
    #pragma unroll
    for (int q = 0; q < 4; q++) {
        float4 w = wrow[q];
        v[q*4+0] = w.x; v[q*4+1] = w.y; v[q*4+2] = w.z; v[q*4+3] = w.w;
    }
    float m = v[0];
    #pragma unroll
    for (int k = 1; k < 16; k++) m = fmaxf(m, v[k]);
    float s = 0.0f;
    #pragma unroll
    for (int k = 0; k < 16; k++) { v[k] = expf(v[k] - m); s += v[k]; }
    float inv = 1.0f / s;

    float c0 = 0.f, c1 = 0.f, c2 = 0.f, c3 = 0.f;
    #pragma unroll
    for (int k = 0; k < 16; k++) {
        float wk = v[k] * inv;
        c0 = fmaf(wk, GATE0[k], c0);
        c1 = fmaf(wk, GATE1[k], c1);
        c2 = fmaf(wk, GATE2[k], c2);
        c3 = fmaf(wk, GATE3[k], c3);
    }

    g_mIdx[j] = (unsigned)idx_a[j] | ((unsigned)idx_b[j] << 13);
    __half2 c01 = __floats2half2_rn(c0, c1);
    __half2 c23 = __floats2half2_rn(c2, c3);
    uint2 rec;
    rec.x = *reinterpret_cast<unsigned*>(&c01);
    rec.y = *reinterpret_cast<unsigned*>(&c23);
    g_coef[j] = rec;
}

// ---------------------------------------------------------------------------
// TMA bulk 1D: one 64KB contiguous group (2 rows) GMEM -> SMEM, mbarrier tx.
// ---------------------------------------------------------------------------
__device__ __forceinline__ void tma_issue(float* smem_dst, const float* gmem_src,
                                          uint64_t* mbar) {
    uint32_t s  = (uint32_t)__cvta_generic_to_shared(smem_dst);
    uint32_t mb = (uint32_t)__cvta_generic_to_shared(mbar);
    asm volatile("mbarrier.arrive.expect_tx.shared.b64 _, [%0], %1;"
                 :: "r"(mb), "r"((unsigned)GROUP_BYTES) : "memory");
    asm volatile("cp.async.bulk.shared::cta.global.mbarrier::complete_tx::bytes "
                 "[%0], [%1], %2, [%3];"
                 :: "r"(s), "l"(gmem_src), "r"((unsigned)GROUP_BYTES), "r"(mb)
                 : "memory");
}

__device__ __forceinline__ void mbar_wait(uint64_t* mbar, unsigned parity) {
    uint32_t mb = (uint32_t)__cvta_generic_to_shared(mbar);
    asm volatile(
        "{\n\t"
        ".reg .pred P1;\n\t"
        "WAIT_LOOP_%=:\n\t"
        "mbarrier.try_wait.parity.acquire.cta.shared::cta.b64 P1, [%0], %1, 0x989680;\n\t"
        "@P1 bra.uni WAIT_DONE_%=;\n\t"
        "bra.uni WAIT_LOOP_%=;\n\t"
        "WAIT_DONE_%=:\n\t"
        "}"
        :: "r"(mb), "r"(parity) : "memory");
}

// ---------------------------------------------------------------------------
// Main: persistent; TMA bulk loads rows (no warp copy work); idx in regs;
// coeffs via __ldg (L1-resident, smem-free); double buffer + work stealing.
// ---------------------------------------------------------------------------
extern "C" __global__ void __launch_bounds__(THREADS, 1)
logic_kernel(const float* __restrict__ x, float* __restrict__ out) {
    extern __shared__ float sm[];             // [2][R*IN_DIM]
    __shared__ __align__(8) uint64_t mbar[2];
    __shared__ int s_q[2];
    const int tid = threadIdx.x;

    // ---- idx slice into registers (once) ----
    unsigned mIdx[KITERS];
    #pragma unroll
    for (int k = 0; k < KITERS; k++) mIdx[k] = g_mIdx[tid + k * THREADS];

    // ---- init barriers + first two steals ----
    if (tid == 0) {
        asm volatile("mbarrier.init.shared.b64 [%0], 1;"
                     :: "r"((uint32_t)__cvta_generic_to_shared(&mbar[0])) : "memory");
        asm volatile("mbarrier.init.shared.b64 [%0], 1;"
                     :: "r"((uint32_t)__cvta_generic_to_shared(&mbar[1])) : "memory");
        s_q[0] = (int)atomicAdd(&g_ctr, 1u);
        s_q[1] = (int)atomicAdd(&g_ctr, 1u);
    }
    __syncthreads();

    int g     = s_q[0];
    int gnext = s_q[1];
    if (tid == 0) {
        if (g     < NGROUPS) tma_issue(sm,                x + (size_t)g     * (R * IN_DIM), &mbar[0]);
        if (gnext < NGROUPS) tma_issue(sm + R * IN_DIM,   x + (size_t)gnext * (R * IN_DIM), &mbar[1]);
    }

    int cur = 0;
    unsigned ph0 = 0, ph1 = 0;

    while (g < NGROUPS) {
        // steal the group that will refill buf[cur] (read after the barrier below)
        if (tid == 0) s_q[cur] = (int)atomicAdd(&g_ctr, 1u);

        // wait current buffer's TMA
        if (cur == 0) { mbar_wait(&mbar[0], ph0); }
        else          { mbar_wait(&mbar[1], ph1); }

        // ---- compute current group ----
        const float* b0 = sm + cur * (R * IN_DIM);
        const float* b1 = b0 + IN_DIM;
        float* o0 = out + (size_t)g * (R * OUT_DIM);
        #pragma unroll
        for (int k = 0; k < KITERS; k++) {
            int j = tid + k * THREADS;
            unsigned pk = mIdx[k];
            unsigned ai = pk & 8191u;
            unsigned bi = pk >> 13;
            uint2 cc = __ldg(&g_coef[j]);                 // LDG.64, L1-resident
            float2 c01 = __half22float2(*reinterpret_cast<const __half2*>(&cc.x));
            float2 c23 = __half22float2(*reinterpret_cast<const __half2*>(&cc.y));
            float a0 = b0[ai], bb0 = b0[bi];
            float a1 = b1[ai], bb1 = b1[bi];
            __stcg(o0 + j,
                   fmaf(c23.y, a0 * bb0, fmaf(c23.x, bb0, fmaf(c01.y, a0, c01.x))));
            __stcg(o0 + OUT_DIM + j,
                   fmaf(c23.y, a1 * bb1, fmaf(c23.x, bb1, fmaf(c01.y, a1, c01.x))));
        }
        if (cur == 0) ph0 ^= 1; else ph1 ^= 1;

        __syncthreads();            // all gathers from buf[cur] done; s_q[cur] visible
        int gnew = s_q[cur];
        if (tid == 0 && gnew < NGROUPS)
            tma_issue(sm + cur * (R * IN_DIM), x + (size_t)gnew * (R * IN_DIM),
                      &mbar[cur]);

        g = gnext;
        gnext = gnew;
        cur ^= 1;
    }
}

// ---------------------------------------------------------------------------
// Launch: x (f32), weight (f32), idx_a (i32), idx_b (i32) -> out (f32)
// ---------------------------------------------------------------------------
extern "C" void kernel_launch(void* const* d_in, const int* in_sizes, int n_in,
                              void* d_out, int out_size) {
    const float* x      = (const float*)d_in[0];
    const float* weight = (const float*)d_in[1];
    const int*   idx_a  = (const int*)d_in[2];
    const int*   idx_b  = (const int*)d_in[3];
    float*       out    = (float*)d_out;

    cudaFuncSetAttribute(logic_kernel,
                         cudaFuncAttributeMaxDynamicSharedMemorySize, SMEM_BYTES);

    prep_kernel<<<OUT_DIM / 256, 256>>>(weight, idx_a, idx_b);
    logic_kernel<<<GRID, THREADS, SMEM_BYTES>>>(x, out);
}